// round 8
// baseline (speedup 1.0000x reference)
#include <cuda_runtime.h>
#include <cstdint>

// CrossNet closed form, persistent CTAs + L2-prefetch pipeline.
//   d_k = x . w_k ; c12=b1.w2, c13=b1.w3, c23=b2.w3 (prologue, per CTA)
//   a1 = d1+1; a2 = a1*d2+c12+1; a3 = a2*(a1*d3+c13)+c23+1
//   out = (a1*a2*a3)*x + (a2*a3)*b1 + a3*b2 + b3
// B=16384, D=2048 fp32. R=4 rows/tile, 512 threads, 444 persistent CTAs (3/SM).
// Next tile is prefetched to L2 (no registers) while the current tile's
// reduction/epilogue runs; current-tile loads then hit L2 (~250cyc).

#define D 2048
#define VEC (D / 4)            // 512 float4 per row
#define THREADS 512
#define NWARP (THREADS / 32)   // 16
#define R 4
#define TILE_BYTES (R * D * 4) // 32768 = 256 x 128B lines
#define NCTA 444               // 3 per SM * 148 SMs

__device__ __forceinline__ float dot4(float4 a, float4 b) {
    return a.x*b.x + a.y*b.y + a.z*b.z + a.w*b.w;
}

__global__ __launch_bounds__(THREADS, 3)
void crossnet_kernel(const float4* __restrict__ x,
                     const float4* __restrict__ w1, const float4* __restrict__ b1,
                     const float4* __restrict__ w2, const float4* __restrict__ b2,
                     const float4* __restrict__ w3, const float4* __restrict__ b3,
                     float4* __restrict__ out, int ntiles)
{
    __shared__ float4 shp1[NWARP], shp2[NWARP], shp3[NWARP]; // per-warp dot partials (4 rows)
    __shared__ float4 sh_c[R];                               // per-row (m, k1, k2, _)
    __shared__ float  sh_k[3];                               // c12, c13, c23

    const int t    = threadIdx.x;
    const int lane = t & 31;
    const int wid  = t >> 5;

    // ---- prologue: cross constants c12=b1.w2, c13=b1.w3, c23=b2.w3 ----
    {
        const float4 bq1 = __ldg(&b1[t]);
        const float4 bq2 = __ldg(&b2[t]);
        const float4 wq2 = __ldg(&w2[t]);
        const float4 wq3 = __ldg(&w3[t]);
        float q12 = dot4(bq1, wq2);
        float q13 = dot4(bq1, wq3);
        float q23 = dot4(bq2, wq3);
        #pragma unroll
        for (int off = 16; off > 0; off >>= 1) {
            q12 += __shfl_xor_sync(0xFFFFFFFFu, q12, off);
            q13 += __shfl_xor_sync(0xFFFFFFFFu, q13, off);
            q23 += __shfl_xor_sync(0xFFFFFFFFu, q23, off);
        }
        if (lane == 0) shp1[wid] = make_float4(q12, q13, q23, 0.0f);
    }
    __syncthreads();
    if (wid == 0) {
        float4 v = (lane < NWARP) ? shp1[lane] : make_float4(0.f, 0.f, 0.f, 0.f);
        #pragma unroll
        for (int off = 8; off > 0; off >>= 1) {
            v.x += __shfl_xor_sync(0xFFFFFFFFu, v.x, off);
            v.y += __shfl_xor_sync(0xFFFFFFFFu, v.y, off);
            v.z += __shfl_xor_sync(0xFFFFFFFFu, v.z, off);
        }
        if (lane == 0) { sh_k[0] = v.x; sh_k[1] = v.y; sh_k[2] = v.z; }
    }
    __syncthreads();

    // ---- prefetch first tile (cold for tile 0..grid-1 anyway; harmless) ----
    if (blockIdx.x < (unsigned)ntiles && t < 256) {
        const char* p = (const char*)x + (size_t)blockIdx.x * TILE_BYTES + t * 128;
        asm volatile("prefetch.global.L2 [%0];" :: "l"(p));
    }

    for (int tile = blockIdx.x; tile < ntiles; tile += gridDim.x) {
        // ---- prefetch NEXT tile to L2 (fire-and-forget, zero registers) ----
        const int nxt = tile + gridDim.x;
        if (nxt < ntiles && t < 256) {
            const char* p = (const char*)x + (size_t)nxt * TILE_BYTES + t * 128;
            asm volatile("prefetch.global.L2 [%0];" :: "l"(p));
        }

        // ---- load current tile (L2 hit from last iteration's prefetch) ----
        const int base = tile * (R * VEC) + t;
        float4 yc[R];
        #pragma unroll
        for (int r = 0; r < R; ++r)
            yc[r] = __ldcs(&x[base + r * VEC]);

        // ---- three dots, batched per weight to cap register pressure ----
        {
            const float4 wv = __ldg(&w1[t]);
            float p[R];
            #pragma unroll
            for (int r = 0; r < R; ++r) p[r] = dot4(yc[r], wv);
            #pragma unroll
            for (int off = 16; off > 0; off >>= 1) {
                #pragma unroll
                for (int r = 0; r < R; ++r)
                    p[r] += __shfl_xor_sync(0xFFFFFFFFu, p[r], off);
            }
            if (lane == 0) shp1[wid] = make_float4(p[0], p[1], p[2], p[3]);
        }
        {
            const float4 wv = __ldg(&w2[t]);
            float p[R];
            #pragma unroll
            for (int r = 0; r < R; ++r) p[r] = dot4(yc[r], wv);
            #pragma unroll
            for (int off = 16; off > 0; off >>= 1) {
                #pragma unroll
                for (int r = 0; r < R; ++r)
                    p[r] += __shfl_xor_sync(0xFFFFFFFFu, p[r], off);
            }
            if (lane == 0) shp2[wid] = make_float4(p[0], p[1], p[2], p[3]);
        }
        {
            const float4 wv = __ldg(&w3[t]);
            float p[R];
            #pragma unroll
            for (int r = 0; r < R; ++r) p[r] = dot4(yc[r], wv);
            #pragma unroll
            for (int off = 16; off > 0; off >>= 1) {
                #pragma unroll
                for (int r = 0; r < R; ++r)
                    p[r] += __shfl_xor_sync(0xFFFFFFFFu, p[r], off);
            }
            if (lane == 0) shp3[wid] = make_float4(p[0], p[1], p[2], p[3]);
        }
        __syncthreads();

        // ---- warp0: cross-warp combine + coefficients ----
        if (wid == 0) {
            const float4 z = make_float4(0.f, 0.f, 0.f, 0.f);
            float4 v1 = (lane < NWARP) ? shp1[lane] : z;
            float4 v2 = (lane < NWARP) ? shp2[lane] : z;
            float4 v3 = (lane < NWARP) ? shp3[lane] : z;
            #pragma unroll
            for (int off = 8; off > 0; off >>= 1) {
                v1.x += __shfl_xor_sync(0xFFFFFFFFu, v1.x, off);
                v1.y += __shfl_xor_sync(0xFFFFFFFFu, v1.y, off);
                v1.z += __shfl_xor_sync(0xFFFFFFFFu, v1.z, off);
                v1.w += __shfl_xor_sync(0xFFFFFFFFu, v1.w, off);
                v2.x += __shfl_xor_sync(0xFFFFFFFFu, v2.x, off);
                v2.y += __shfl_xor_sync(0xFFFFFFFFu, v2.y, off);
                v2.z += __shfl_xor_sync(0xFFFFFFFFu, v2.z, off);
                v2.w += __shfl_xor_sync(0xFFFFFFFFu, v2.w, off);
                v3.x += __shfl_xor_sync(0xFFFFFFFFu, v3.x, off);
                v3.y += __shfl_xor_sync(0xFFFFFFFFu, v3.y, off);
                v3.z += __shfl_xor_sync(0xFFFFFFFFu, v3.z, off);
                v3.w += __shfl_xor_sync(0xFFFFFFFFu, v3.w, off);
            }
            if (lane == 0) {
                const float c12 = sh_k[0], c13 = sh_k[1], c23 = sh_k[2];
                const float d1[R] = {v1.x, v1.y, v1.z, v1.w};
                const float d2[R] = {v2.x, v2.y, v2.z, v2.w};
                const float d3[R] = {v3.x, v3.y, v3.z, v3.w};
                #pragma unroll
                for (int r = 0; r < R; ++r) {
                    const float a1 = d1[r] + 1.0f;
                    const float a2 = fmaf(a1, d2[r], c12) + 1.0f;
                    const float a3 = fmaf(a2, fmaf(a1, d3[r], c13), c23) + 1.0f;
                    const float k1 = a2 * a3;
                    const float m  = a1 * k1;
                    sh_c[r] = make_float4(m, k1, a3, 0.0f);
                }
            }
        }
        __syncthreads();

        // ---- epilogue: out = m*x + k1*b1 + k2*b2 + b3 ----
        const float4 bv1 = __ldg(&b1[t]);
        const float4 bv2 = __ldg(&b2[t]);
        const float4 bv3 = __ldg(&b3[t]);
        #pragma unroll
        for (int r = 0; r < R; ++r) {
            const float4 c = sh_c[r];
            float4 o;
            o.x = fmaf(yc[r].x, c.x, fmaf(bv1.x, c.y, fmaf(bv2.x, c.z, bv3.x)));
            o.y = fmaf(yc[r].y, c.x, fmaf(bv1.y, c.y, fmaf(bv2.y, c.z, bv3.y)));
            o.z = fmaf(yc[r].z, c.x, fmaf(bv1.z, c.y, fmaf(bv2.z, c.z, bv3.z)));
            o.w = fmaf(yc[r].w, c.x, fmaf(bv1.w, c.y, fmaf(bv2.w, c.z, bv3.w)));
            __stcs(&out[base + r * VEC], o);
        }
    }
}

extern "C" void kernel_launch(void* const* d_in, const int* in_sizes, int n_in,
                              void* d_out, int out_size)
{
    const float4* x  = (const float4*)d_in[0];
    const float4* w1 = (const float4*)d_in[1];
    const float4* b1 = (const float4*)d_in[2];
    const float4* w2 = (const float4*)d_in[3];
    const float4* b2 = (const float4*)d_in[4];
    const float4* w3 = (const float4*)d_in[5];
    const float4* b3 = (const float4*)d_in[6];
    float4* out = (float4*)d_out;

    const int B = in_sizes[0] / D;    // 16384
    const int ntiles = B / R;         // 4096
    const int grid = (ntiles < NCTA) ? ntiles : NCTA;
    crossnet_kernel<<<grid, THREADS>>>(x, w1, b1, w2, b2, w3, b3, out, ntiles);
}

// round 10
// speedup vs baseline: 1.2603x; 1.2603x over previous
#include <cuda_runtime.h>

// CrossNet closed form, persistent CTAs + register double-buffer pipeline
// + split named barriers (correct producer/consumer counts) + w/b in smem.
//   d_k = x . w_k ; c12=b1.w2, c13=b1.w3, c23=b2.w3 (prologue, per CTA)
//   a1 = d1+1; a2 = a1*d2+c12+1; a3 = a2*(a1*d3+c13)+c23+1
//   out = (a1*a2*a3)*x + (a2*a3)*b1 + a3*b2 + b3
// B=16384, D=2048 fp32. R=4 rows/tile, 512 threads, 296 persistent CTAs.
// Barrier protocol (512 total arrivals each):
//   bar1: warps 1..15 arrive (480) + warp0 sync (32)
//   bar2: warp0 arrive (32) + warps 1..15 sync (480)
// Next-tile loads are issued by every warp BEFORE it blocks, so DRAM
// requests stay outstanding through the reduce window.

#define D 2048
#define VEC (D / 4)            // 512 float4 per row
#define THREADS 512
#define NWARP (THREADS / 32)   // 16
#define R 4
#define NCTA 296               // 2 per SM * 148 SMs

#define BAR_ARRIVE(id) asm volatile("bar.arrive %0, %1;" :: "r"(id), "r"(THREADS) : "memory")
#define BAR_SYNC(id)   asm volatile("bar.sync %0, %1;"   :: "r"(id), "r"(THREADS) : "memory")

__device__ __forceinline__ float dot4(float4 a, float4 b) {
    return a.x*b.x + a.y*b.y + a.z*b.z + a.w*b.w;
}

__global__ __launch_bounds__(THREADS, 2)
void crossnet_kernel(const float4* __restrict__ x,
                     const float4* __restrict__ w1, const float4* __restrict__ b1,
                     const float4* __restrict__ w2, const float4* __restrict__ b2,
                     const float4* __restrict__ w3, const float4* __restrict__ b3,
                     float4* __restrict__ out, int ntiles)
{
    __shared__ float4 sw1[VEC], sw2[VEC], sw3[VEC];          // weights (24 KB)
    __shared__ float4 sb1[VEC], sb2[VEC];                    // biases 1,2 (16 KB)
    __shared__ float4 shp1[NWARP], shp2[NWARP], shp3[NWARP]; // per-warp dot partials
    __shared__ float4 sh_c[R];                               // per-row (m, k1, k2, _)
    __shared__ float  sh_k[3];                               // c12, c13, c23

    const int t    = threadIdx.x;
    const int lane = t & 31;
    const int wid  = t >> 5;

    // ---- prologue: stage w/b in smem + cross constants ----
    {
        const float4 wq1 = __ldg(&w1[t]);
        const float4 wq2 = __ldg(&w2[t]);
        const float4 wq3 = __ldg(&w3[t]);
        const float4 bq1 = __ldg(&b1[t]);
        const float4 bq2 = __ldg(&b2[t]);
        sw1[t] = wq1; sw2[t] = wq2; sw3[t] = wq3;
        sb1[t] = bq1; sb2[t] = bq2;

        float q12 = dot4(bq1, wq2);
        float q13 = dot4(bq1, wq3);
        float q23 = dot4(bq2, wq3);
        #pragma unroll
        for (int off = 16; off > 0; off >>= 1) {
            q12 += __shfl_xor_sync(0xFFFFFFFFu, q12, off);
            q13 += __shfl_xor_sync(0xFFFFFFFFu, q13, off);
            q23 += __shfl_xor_sync(0xFFFFFFFFu, q23, off);
        }
        if (lane == 0) shp1[wid] = make_float4(q12, q13, q23, 0.0f);
    }
    __syncthreads();
    if (wid == 0) {
        float4 v = (lane < NWARP) ? shp1[lane] : make_float4(0.f, 0.f, 0.f, 0.f);
        #pragma unroll
        for (int off = 8; off > 0; off >>= 1) {
            v.x += __shfl_xor_sync(0xFFFFFFFFu, v.x, off);
            v.y += __shfl_xor_sync(0xFFFFFFFFu, v.y, off);
            v.z += __shfl_xor_sync(0xFFFFFFFFu, v.z, off);
        }
        if (lane == 0) { sh_k[0] = v.x; sh_k[1] = v.y; sh_k[2] = v.z; }
    }

    // bias3 stays in registers (loop-invariant LDG, L1-hot across CTAs)
    const float4 bv3 = __ldg(&b3[t]);

    // ---- pipeline prologue: load first tile ----
    int tile = blockIdx.x;
    float4 yc[R];
    if (tile < ntiles) {
        const int base = tile * (R * VEC) + t;
        #pragma unroll
        for (int r = 0; r < R; ++r)
            yc[r] = __ldcs(&x[base + r * VEC]);
    }
    __syncthreads();

    for (; tile < ntiles; tile += gridDim.x) {
        // ---- three dots on current tile (weights via LDS) ----
        {
            const float4 wv = sw1[t];
            float p[R];
            #pragma unroll
            for (int r = 0; r < R; ++r) p[r] = dot4(yc[r], wv);
            #pragma unroll
            for (int off = 16; off > 0; off >>= 1) {
                #pragma unroll
                for (int r = 0; r < R; ++r)
                    p[r] += __shfl_xor_sync(0xFFFFFFFFu, p[r], off);
            }
            if (lane == 0) shp1[wid] = make_float4(p[0], p[1], p[2], p[3]);
        }
        {
            const float4 wv = sw2[t];
            float p[R];
            #pragma unroll
            for (int r = 0; r < R; ++r) p[r] = dot4(yc[r], wv);
            #pragma unroll
            for (int off = 16; off > 0; off >>= 1) {
                #pragma unroll
                for (int r = 0; r < R; ++r)
                    p[r] += __shfl_xor_sync(0xFFFFFFFFu, p[r], off);
            }
            if (lane == 0) shp2[wid] = make_float4(p[0], p[1], p[2], p[3]);
        }
        {
            const float4 wv = sw3[t];
            float p[R];
            #pragma unroll
            for (int r = 0; r < R; ++r) p[r] = dot4(yc[r], wv);
            #pragma unroll
            for (int off = 16; off > 0; off >>= 1) {
                #pragma unroll
                for (int r = 0; r < R; ++r)
                    p[r] += __shfl_xor_sync(0xFFFFFFFFu, p[r], off);
            }
            if (lane == 0) shp3[wid] = make_float4(p[0], p[1], p[2], p[3]);
        }

        // ---- producers signal partials; everyone issues next-tile loads ----
        if (wid != 0) BAR_ARRIVE(1);      // 480 arrivals

        const int nxt = tile + gridDim.x;
        float4 yn[R];
        if (nxt < ntiles) {
            const int nbase = nxt * (R * VEC) + t;
            #pragma unroll
            for (int r = 0; r < R; ++r)
                yn[r] = __ldcs(&x[nbase + r * VEC]);
        }

        if (wid == 0) {
            BAR_SYNC(1);                  // +32 -> 512: all partials visible
            const float4 z = make_float4(0.f, 0.f, 0.f, 0.f);
            float4 v1 = (lane < NWARP) ? shp1[lane] : z;
            float4 v2 = (lane < NWARP) ? shp2[lane] : z;
            float4 v3 = (lane < NWARP) ? shp3[lane] : z;
            #pragma unroll
            for (int off = 8; off > 0; off >>= 1) {
                v1.x += __shfl_xor_sync(0xFFFFFFFFu, v1.x, off);
                v1.y += __shfl_xor_sync(0xFFFFFFFFu, v1.y, off);
                v1.z += __shfl_xor_sync(0xFFFFFFFFu, v1.z, off);
                v1.w += __shfl_xor_sync(0xFFFFFFFFu, v1.w, off);
                v2.x += __shfl_xor_sync(0xFFFFFFFFu, v2.x, off);
                v2.y += __shfl_xor_sync(0xFFFFFFFFu, v2.y, off);
                v2.z += __shfl_xor_sync(0xFFFFFFFFu, v2.z, off);
                v2.w += __shfl_xor_sync(0xFFFFFFFFu, v2.w, off);
                v3.x += __shfl_xor_sync(0xFFFFFFFFu, v3.x, off);
                v3.y += __shfl_xor_sync(0xFFFFFFFFu, v3.y, off);
                v3.z += __shfl_xor_sync(0xFFFFFFFFu, v3.z, off);
                v3.w += __shfl_xor_sync(0xFFFFFFFFu, v3.w, off);
            }
            if (lane == 0) {
                const float c12 = sh_k[0], c13 = sh_k[1], c23 = sh_k[2];
                const float d1[R] = {v1.x, v1.y, v1.z, v1.w};
                const float d2[R] = {v2.x, v2.y, v2.z, v2.w};
                const float d3[R] = {v3.x, v3.y, v3.z, v3.w};
                #pragma unroll
                for (int r = 0; r < R; ++r) {
                    const float a1 = d1[r] + 1.0f;
                    const float a2 = fmaf(a1, d2[r], c12) + 1.0f;
                    const float a3 = fmaf(a2, fmaf(a1, d3[r], c13), c23) + 1.0f;
                    const float k1 = a2 * a3;
                    const float m  = a1 * k1;
                    sh_c[r] = make_float4(m, k1, a3, 0.0f);
                }
            }
            __syncwarp();
            BAR_ARRIVE(2);                // 32 arrivals: publish coefficients
        } else {
            BAR_SYNC(2);                  // +480 -> 512 (yn loads in flight)
        }

        // ---- epilogue: out = m*x + k1*b1 + k2*b2 + b3 ----
        const float4 bv1 = sb1[t];
        const float4 bv2 = sb2[t];
        const int base = tile * (R * VEC) + t;
        #pragma unroll
        for (int r = 0; r < R; ++r) {
            const float4 c = sh_c[r];
            float4 o;
            o.x = fmaf(yc[r].x, c.x, fmaf(bv1.x, c.y, fmaf(bv2.x, c.z, bv3.x)));
            o.y = fmaf(yc[r].y, c.x, fmaf(bv1.y, c.y, fmaf(bv2.y, c.z, bv3.y)));
            o.z = fmaf(yc[r].z, c.x, fmaf(bv1.z, c.y, fmaf(bv2.z, c.z, bv3.z)));
            o.w = fmaf(yc[r].w, c.x, fmaf(bv1.w, c.y, fmaf(bv2.w, c.z, bv3.w)));
            __stcs(&out[base + r * VEC], o);
        }

        // ---- rotate pipeline ----
        #pragma unroll
        for (int r = 0; r < R; ++r) yc[r] = yn[r];
    }
}

extern "C" void kernel_launch(void* const* d_in, const int* in_sizes, int n_in,
                              void* d_out, int out_size)
{
    const float4* x  = (const float4*)d_in[0];
    const float4* w1 = (const float4*)d_in[1];
    const float4* b1 = (const float4*)d_in[2];
    const float4* w2 = (const float4*)d_in[3];
    const float4* b2 = (const float4*)d_in[4];
    const float4* w3 = (const float4*)d_in[5];
    const float4* b3 = (const float4*)d_in[6];
    float4* out = (float4*)d_out;

    const int B = in_sizes[0] / D;    // 16384
    const int ntiles = B / R;         // 4096
    const int grid = (ntiles < NCTA) ? ntiles : NCTA;
    crossnet_kernel<<<grid, THREADS>>>(x, w1, b1, w2, b2, w3, b3, out, ntiles);
}